// round 15
// baseline (speedup 1.0000x reference)
#include <cuda_runtime.h>
#include <cuda_fp16.h>

#define N_NODES 10000
#define N_EDGES 320000
#define D_IN    128
#define D_HID   64
#define D_OUT   16
#define NH      (N_NODES * D_HID)
#define AAM     5
#define PAD     128                  // padded edge-row length
#define TPB         512
#define BLK_PER_SM  2
#define GRID_BLOCKS 296              // 148 SMs x 2 blocks guaranteed resident
#define WPB         (TPB / 32)       // 16
#define NWARPS      (GRID_BLOCKS * WPB)          // 4736
#define NTHREADS    (GRID_BLOCKS * TPB)
#define NSPMM       9                // 5 history + 4 Anderson spmm phases

typedef unsigned long long ull;

// ---------------- device scratch ----------------
__device__ float  g_b[NH];
__device__ float  g_u[NH];                  // written only by Anderson combines
__device__ __half g_wbuf[2][NH];            // fp16 SPMM input (only gather reads it)
__device__ float  g_F[AAM][NH];
__device__ float  g_G[AAM][NH];
__device__ float  g_ThT[D_HID * D_HID];     // ThT[k*64+c] = Theta[c][k]
__device__ int    g_cur[N_NODES];           // zero at launch entry (re-zeroed at kernel tail)
__device__ __align__(16) int2 g_edge[N_NODES * PAD];   // padded edge rows
__device__ int    g_tick[NSPMM];            // per-phase pair ticket counters
__device__ double g_GGbuf[2][15];
__device__ double g_GGrow[2][5];
__device__ unsigned          g_bar_cnt;
__device__ volatile unsigned g_bar_gen;

union SmemU {
    struct { float M[64][128]; float fct[64]; } th;            // 33 KB (setup)
    struct {
        ulonglong2 T[32][32];     // 16KB: {A[m][l], B[m][l]} packed Theta
        ulonglong2 s[WPB][32];    // 8KB: per-warp staged (sA, sB) / encoder x rows
    } mix;                        // 24 KB
};

// ---------------- f32x2 helpers ----------------
__device__ __forceinline__ void fma2(ull& d, ull a, ull b) {
    asm("fma.rn.f32x2 %0, %1, %2, %0;" : "+l"(d) : "l"(a), "l"(b));
}
__device__ __forceinline__ ull pack2(float2 v) {
    ull r; asm("mov.b64 %0, {%1, %2};" : "=l"(r) : "f"(v.x), "f"(v.y)); return r;
}
__device__ __forceinline__ float2 unpack2(ull v) {
    float2 r; asm("mov.b64 {%0, %1}, %2;" : "=f"(r.x), "=f"(r.y) : "l"(v)); return r;
}
__device__ __forceinline__ float2 gfma(float2 a, float w, float2 v) {
    a.x = fmaf(w, v.x, a.x); a.y = fmaf(w, v.y, a.y); return a;
}

// ---------------- software grid barrier ----------------
__device__ __forceinline__ void gbar() {
    __syncthreads();
    if (threadIdx.x == 0) {
        __threadfence();
        unsigned gen = g_bar_gen;
        if (atomicAdd(&g_bar_cnt, 1u) == GRID_BLOCKS - 1u) {
            g_bar_cnt = 0u;
            __threadfence();
            g_bar_gen = gen + 1u;
        } else {
            while (g_bar_gen == gen) { __nanosleep(32); }
        }
        __threadfence();
    }
    __syncthreads();
}

// ---------------- Cayley: Theta = (I+Om)^-1 (I-Om) ----------------
__device__ void theta_phase(const float* __restrict__ B, SmemU* su) {
    int tid = threadIdx.x;
    for (int idx = tid; idx < 64 * 64; idx += TPB) {
        int i = idx >> 6, j = idx & 63;
        float om = 0.5f * (B[i * 64 + j] - B[j * 64 + i]);
        float e  = (i == j) ? 1.f : 0.f;
        su->th.M[i][j]      = e + om;
        su->th.M[i][64 + j] = e - om;
    }
    __syncthreads();
    for (int k = 0; k < 64; k++) {
        float inv = 1.f / su->th.M[k][k];
        __syncthreads();
        for (int j = tid; j < 128; j += TPB) su->th.M[k][j] *= inv;
        __syncthreads();
        for (int r = tid; r < 64; r += TPB) su->th.fct[r] = su->th.M[r][k];
        __syncthreads();
        for (int idx = tid; idx < 64 * 128; idx += TPB) {
            int r = idx >> 7, j = idx & 127;
            if (r != k) su->th.M[r][j] -= su->th.fct[r] * su->th.M[k][j];
        }
        __syncthreads();
    }
    for (int idx = tid; idx < 64 * 64; idx += TPB) {
        int k = idx >> 6, c = idx & 63;
        g_ThT[idx] = su->th.M[c][64 + k];
    }
}

// ---------------- encoder + b/w0 (x staged through smem, coalesced) ----------------
__device__ void encode_phase(const float* __restrict__ x, const float* __restrict__ W,
                             const float* __restrict__ bias, SmemU* su) {
    int warp = threadIdx.x >> 5, cp = threadIdx.x & 31;
    int g = blockIdx.x * WPB + warp;
    const float2* __restrict__ W2 = (const float2*)W;
    float4* sx = (float4*)&su->mix.s[warp][0];   // 512B = one x row
    float2 bsv = ((const float2*)bias)[cp];
    for (int node = g; node < N_NODES; node += NWARPS) {
        sx[cp] = ((const float4*)(x + node * D_IN))[cp];
        __syncwarp();
        const float* xs = (const float*)sx;
        float2 acc = bsv;
#pragma unroll 16
        for (int k = 0; k < D_IN; k++) {
            float  xk = xs[k];
            float2 w2 = W2[k * 32 + cp];
            acc.x = fmaf(xk, w2.x, acc.x);
            acc.y = fmaf(xk, w2.y, acc.y);
        }
        __syncwarp();
        int row = node * 32 + cp;
        ((float2*)g_b)[row] = acc;
        ((__half2*)g_wbuf[0])[row] =
            __floats2half2_rn(2.f * fmaxf(acc.x, 0.f), 2.f * fmaxf(acc.y, 0.f));
    }
}

// ---------------- branch-free interleaved dual-node gather (counts pre-rounded to 4) ----
__device__ __forceinline__ void gather2(const int2* __restrict__ eg,
                                        const __half2* __restrict__ wv,
                                        int bA, int hcA, int bB, int hcB,
                                        int lane, float2& outA, float2& outB) {
    const int4* __restrict__ e4A = (const int4*)(eg + bA);
    const int4* __restrict__ e4B = (const int4*)(eg + bB);
    float2 aA0 = {0.f, 0.f}, aA1 = {0.f, 0.f};
    float2 aB0 = {0.f, 0.f}, aB1 = {0.f, 0.f};
    int hA = 0, hB = 0;
    while (hA + 2 <= hcA && hB + 2 <= hcB) {
        int4 dA0 = e4A[hA], dA1 = e4A[hA + 1];
        int4 dB0 = e4B[hB], dB1 = e4B[hB + 1];
        __half2 vA0 = wv[dA0.x * 32 + lane], vA1 = wv[dA0.z * 32 + lane];
        __half2 vA2 = wv[dA1.x * 32 + lane], vA3 = wv[dA1.z * 32 + lane];
        __half2 vB0 = wv[dB0.x * 32 + lane], vB1 = wv[dB0.z * 32 + lane];
        __half2 vB2 = wv[dB1.x * 32 + lane], vB3 = wv[dB1.z * 32 + lane];
        aA0 = gfma(aA0, __int_as_float(dA0.y), __half22float2(vA0));
        aA1 = gfma(aA1, __int_as_float(dA0.w), __half22float2(vA1));
        aA0 = gfma(aA0, __int_as_float(dA1.y), __half22float2(vA2));
        aA1 = gfma(aA1, __int_as_float(dA1.w), __half22float2(vA3));
        aB0 = gfma(aB0, __int_as_float(dB0.y), __half22float2(vB0));
        aB1 = gfma(aB1, __int_as_float(dB0.w), __half22float2(vB1));
        aB0 = gfma(aB0, __int_as_float(dB1.y), __half22float2(vB2));
        aB1 = gfma(aB1, __int_as_float(dB1.w), __half22float2(vB3));
        hA += 2; hB += 2;
    }
    for (; hA + 2 <= hcA; hA += 2) {
        int4 d0 = e4A[hA], d1 = e4A[hA + 1];
        __half2 v0 = wv[d0.x * 32 + lane], v1 = wv[d0.z * 32 + lane];
        __half2 v2 = wv[d1.x * 32 + lane], v3 = wv[d1.z * 32 + lane];
        aA0 = gfma(aA0, __int_as_float(d0.y), __half22float2(v0));
        aA1 = gfma(aA1, __int_as_float(d0.w), __half22float2(v1));
        aA0 = gfma(aA0, __int_as_float(d1.y), __half22float2(v2));
        aA1 = gfma(aA1, __int_as_float(d1.w), __half22float2(v3));
    }
    for (; hB + 2 <= hcB; hB += 2) {
        int4 d0 = e4B[hB], d1 = e4B[hB + 1];
        __half2 v0 = wv[d0.x * 32 + lane], v1 = wv[d0.z * 32 + lane];
        __half2 v2 = wv[d1.x * 32 + lane], v3 = wv[d1.z * 32 + lane];
        aB0 = gfma(aB0, __int_as_float(d0.y), __half22float2(v0));
        aB1 = gfma(aB1, __int_as_float(d0.w), __half22float2(v1));
        aB0 = gfma(aB0, __int_as_float(d1.y), __half22float2(v2));
        aB1 = gfma(aB1, __int_as_float(d1.w), __half22float2(v3));
    }
    outA = make_float2(aA0.x + aA1.x, aA0.y + aA1.y);
    outB = make_float2(aB0.x + aB1.x, aB0.y + aB1.y);
}

// ---------------- per-node epilogue ----------------
__device__ __forceinline__ void epilogue(int node, int lane, float2 mix, int slot,
                                         int npairs, int wr_next, int wr_g,
                                         const float* __restrict__ usrc,
                                         __half* __restrict__ wdst, float* p) {
    int row = node * 32 + lane;
    float2 bb = ((const float2*)g_b)[row];
    float2 uu = ((const float2*)usrc)[row];
    float2 val = make_float2(bb.x + 0.5f * mix.x, bb.y + 0.5f * mix.y);
    ((float2*)g_F[slot])[row] = val;
    float2 gn = make_float2(val.x - uu.x, val.y - uu.y);
    if (wr_g) ((float2*)g_G[slot])[row] = gn;
    if (wr_next) {
        ((__half2*)wdst)[row] =
            __floats2half2_rn(2.f * fmaxf(val.x, 0.f) - val.x + bb.x,
                              2.f * fmaxf(val.y, 0.f) - val.y + bb.y);
    }
    for (int j = 0; j < npairs; ++j) {
        float2 gj = (j == slot) ? gn : ((const float2*)g_G[j])[row];
        p[j] = fmaf(gn.x, gj.x, fmaf(gn.y, gj.y, p[j]));
    }
}

// ---------------- fused SPMM: hybrid static+ticket scheduling ----------------
__device__ void spmm_phase(int ph, int slot, int npairs, double* target,
                           int wr_next, int wr_g,
                           const __half* __restrict__ wsrc,
                           const float* __restrict__ usrc,
                           __half* __restrict__ wdst,
                           SmemU* su, double (*red)[5]) {
    int warp = threadIdx.x >> 5, lane = threadIdx.x & 31;
    int w = blockIdx.x * WPB + warp;
    const int2*    __restrict__ eg = g_edge;
    const __half2* __restrict__ wv = (const __half2*)wsrc;
    float p[5];
#pragma unroll
    for (int j = 0; j < 5; j++) p[j] = 0.f;

    // prefetch first ticket (latency hidden under static node)
    int t;
    if (lane == 0) t = atomicAdd(&g_tick[ph], 1);
    t = __shfl_sync(0xffffffffu, t, 0);

    // static single node: n = w  (w < NWARPS <= N_NODES)
    {
        int n = w;
        int hcA = ((g_cur[n] + 3) & ~3) >> 1;
        float2 acc, dummy;
        gather2(eg, wv, n * PAD, hcA, n * PAD, 0, lane, acc, dummy);
        __syncwarp();
        su->mix.s[warp][lane] = make_ulonglong2(pack2(acc), 0ull);
        __syncwarp();
        ull PA = 0ull, QA = 0ull;
#pragma unroll
        for (int m = 0; m < 32; ++m) {
            ulonglong2 sp = su->mix.s[warp][m];
            ulonglong2 T  = su->mix.T[m][lane];
            fma2(PA, T.x, sp.x);
            fma2(QA, T.y, sp.x);
        }
        float2 pA = unpack2(PA), qA = unpack2(QA);
        epilogue(n, lane, make_float2(pA.x + pA.y, qA.x + qA.y),
                 slot, npairs, wr_next, wr_g, usrc, wdst, p);
    }

    // ticketed pairs: nodes [NWARPS, N_NODES) in pairs; next ticket grabbed early
    int n = NWARPS + t * 2;
    while (n < N_NODES) {
        if (lane == 0) t = atomicAdd(&g_tick[ph], 1);
        t = __shfl_sync(0xffffffffu, t, 0);

        int hcA = ((g_cur[n] + 3) & ~3) >> 1;
        int hcB = ((g_cur[n + 1] + 3) & ~3) >> 1;
        float2 accA, accB;
        gather2(eg, wv, n * PAD, hcA, (n + 1) * PAD, hcB, lane, accA, accB);

        __syncwarp();
        su->mix.s[warp][lane] = make_ulonglong2(pack2(accA), pack2(accB));
        __syncwarp();

        ull PA = 0ull, QA = 0ull, PB = 0ull, QB = 0ull;
#pragma unroll
        for (int m = 0; m < 32; ++m) {
            ulonglong2 sp = su->mix.s[warp][m];   // broadcast LDS.128
            ulonglong2 T  = su->mix.T[m][lane];   // conflict-free LDS.128
            fma2(PA, T.x, sp.x); fma2(QA, T.y, sp.x);
            fma2(PB, T.x, sp.y); fma2(QB, T.y, sp.y);
        }
        float2 pA = unpack2(PA), qA = unpack2(QA);
        float2 pB = unpack2(PB), qB = unpack2(QB);
        epilogue(n,     lane, make_float2(pA.x + pA.y, qA.x + qA.y),
                 slot, npairs, wr_next, wr_g, usrc, wdst, p);
        epilogue(n + 1, lane, make_float2(pB.x + pB.y, qB.x + qB.y),
                 slot, npairs, wr_next, wr_g, usrc, wdst, p);
        n = NWARPS + t * 2;
    }

#pragma unroll
    for (int j = 0; j < 5; ++j)
        for (int off = 16; off > 0; off >>= 1)
            p[j] += __shfl_down_sync(0xffffffffu, p[j], off);
    __syncthreads();
    if (lane == 0)
        for (int j = 0; j < 5; ++j) red[warp][j] = (double)p[j];
    __syncthreads();
    if (threadIdx.x < npairs) {
        int j = threadIdx.x;
        double s = 0.0;
        for (int ww = 0; ww < WPB; ww++) s += red[ww][j];
        atomicAdd(&target[j], s);
    }
}

// ---------------- combine(k): Gram merge + 5x5 solve + u_new (+ fused decode at k=4) ----------------
__device__ void combine_phase(int k, float* sa, const float* __restrict__ decW,
                              float* __restrict__ out) {
    if (threadIdx.x == 0) {
        double M[5][5];
        const double* base = g_GGbuf[k & 1];
        int c = 0;
        for (int i = 0; i < 5; i++)
            for (int j = 0; j <= i; j++) { M[i][j] = base[c]; M[j][i] = base[c]; c++; }
        if (k > 0) {
            int idx = k - 1;
            const double* row = g_GGrow[(k - 1) & 1];
            for (int j = 0; j < 5; j++) { M[idx][j] = row[j]; M[j][idx] = row[j]; }
        }
        if (blockIdx.x == 0 && k < AAM - 1) {
            c = 0;
            for (int i = 0; i < 5; i++)
                for (int j = 0; j <= i; j++) g_GGbuf[(k + 1) & 1][c++] = M[i][j];
            for (int j = 0; j < 5; j++) g_GGrow[k & 1][j] = 0.0;
        }
        float A[5][6];
        for (int i = 0; i < 5; i++) {
            for (int j = 0; j < 5; j++) A[i][j] = (float)M[i][j];
            A[i][i] += 1e-4f;
            A[i][5] = 1.f;
        }
        for (int kk = 0; kk < 5; kk++) {
            int piv = kk; float mx = fabsf(A[kk][kk]);
            for (int r = kk + 1; r < 5; r++)
                if (fabsf(A[r][kk]) > mx) { mx = fabsf(A[r][kk]); piv = r; }
            if (piv != kk)
                for (int j = 0; j < 6; j++) { float t = A[kk][j]; A[kk][j] = A[piv][j]; A[piv][j] = t; }
            float inv = 1.f / A[kk][kk];
            for (int r = kk + 1; r < 5; r++) {
                float f = A[r][kk] * inv;
                for (int j = kk; j < 6; j++) A[r][j] -= f * A[kk][j];
            }
        }
        float a[5];
        for (int kk = 4; kk >= 0; kk--) {
            float s = A[kk][5];
            for (int j = kk + 1; j < 5; j++) s -= A[kk][j] * a[j];
            a[kk] = s / A[kk][kk];
        }
        float sum = a[0] + a[1] + a[2] + a[3] + a[4];
        for (int j = 0; j < 5; j++) sa[j] = a[j] / sum;
    }
    __syncthreads();
    float a0 = sa[0], a1 = sa[1], a2 = sa[2], a3 = sa[3], a4 = sa[4];

    int warp = threadIdx.x >> 5, lane = threadIdx.x & 31;
    int g = blockIdx.x * WPB + warp;
    const float2* F0 = (const float2*)g_F[0];
    const float2* F1 = (const float2*)g_F[1];
    const float2* F2 = (const float2*)g_F[2];
    const float2* F3 = (const float2*)g_F[3];
    const float2* F4 = (const float2*)g_F[4];
    for (int node = g; node < N_NODES; node += NWARPS) {
        int idx = node * 32 + lane;
        float2 f0 = F0[idx], f1 = F1[idx], f2 = F2[idx], f3 = F3[idx], f4 = F4[idx];
        float2 un;
        un.x = a0 * f0.x + a1 * f1.x + a2 * f2.x + a3 * f3.x + a4 * f4.x;
        un.y = a0 * f0.y + a1 * f1.y + a2 * f2.y + a3 * f3.y + a4 * f4.y;
        if (k < AAM - 1) {
            ((float2*)g_u)[idx] = un;
            float2 bb = ((const float2*)g_b)[idx];
            ((__half2*)g_wbuf[0])[idx] =
                __floats2half2_rn(2.f * fmaxf(un.x, 0.f) - un.x + bb.x,
                                  2.f * fmaxf(un.y, 0.f) - un.y + bb.y);
        } else {
            float rx = fmaxf(un.x, 0.f), ry = fmaxf(un.y, 0.f);
            int o = lane & 15, half = lane >> 4;
            float acc = 0.f;
#pragma unroll
            for (int i = 0; i < 16; i++) {
                int m = half * 16 + i;
                float sx = __shfl_sync(0xffffffffu, rx, m);
                float sy = __shfl_sync(0xffffffffu, ry, m);
                acc = fmaf(sx, decW[(2 * m) * 16 + o], acc);
                acc = fmaf(sy, decW[(2 * m + 1) * 16 + o], acc);
            }
            acc += __shfl_down_sync(0xffffffffu, acc, 16);
            if (half == 0) out[node * 16 + o] = acc;
        }
    }
}

// ---------------- the single persistent kernel ----------------
__global__ void __launch_bounds__(TPB, BLK_PER_SM) k_mega(
    const float* __restrict__ x, const int* __restrict__ ei,
    const float* __restrict__ ew, const float* __restrict__ encW,
    const float* __restrict__ encb, const float* __restrict__ cayB,
    const float* __restrict__ decW, float* __restrict__ out)
{
    __shared__ SmemU su;
    __shared__ double red[WPB][5];
    __shared__ float sa[5];

    const int* src = ei;
    const int* dst = ei + N_EDGES;
    int gtid = blockIdx.x * TPB + threadIdx.x;

    // Phase 1: one-pass padded-row scatter (g_cur pre-zeroed) || encoder
    //          || zero GGbuf[0] + tickets
    for (int e = gtid; e < N_EDGES; e += NTHREADS) {
        int d = dst[e];
        int pos = atomicAdd(&g_cur[d], 1);
        g_edge[d * PAD + pos] = make_int2(src[e], __float_as_int(ew[e]));
    }
    if (gtid < 15) g_GGbuf[0][gtid] = 0.0;
    if (gtid >= 32 && gtid < 32 + NSPMM) g_tick[gtid - 32] = 0;
    encode_phase(x, encW, encb, &su);
    gbar();

    // Phase 2: Cayley theta (block 1) || zero-fill row padding to multiple of 4 (others)
    if (blockIdx.x == 1) {
        theta_phase(cayB, &su);
    } else {
        int bid = (blockIdx.x == 0) ? 0 : blockIdx.x - 1;   // 0..GRID_BLOCKS-2
        int base = bid * TPB + threadIdx.x;
        for (int i = base; i < N_NODES; i += (GRID_BLOCKS - 1) * TPB) {
            int c = g_cur[i];
            int cr = (c + 3) & ~3;
            for (int e = c; e < cr; e++)
                g_edge[i * PAD + e] = make_int2(0, 0);   // w = 0.0f
        }
    }
    gbar();

    // Phase 3: stage packed Theta into shared (all blocks)
    for (int i = threadIdx.x; i < 1024; i += TPB) {
        int m = i >> 5, l = i & 31;
        float a0 = g_ThT[(2 * m) * 64 + 2 * l];
        float a1 = g_ThT[(2 * m + 1) * 64 + 2 * l];
        float b0 = g_ThT[(2 * m) * 64 + 2 * l + 1];
        float b1 = g_ThT[(2 * m + 1) * 64 + 2 * l + 1];
        su.mix.T[m][l] = make_ulonglong2(pack2(make_float2(a0, a1)),
                                         pack2(make_float2(b0, b1)));
    }
    gbar();

    // history: 5 PR sweeps (w ping-pong); uu read from b / F[i-1]
    for (int i = 0; i < AAM; i++) {
        spmm_phase(i, i, i + 1, &g_GGbuf[0][i * (i + 1) / 2], (i < AAM - 1) ? 1 : 0, 1,
                   g_wbuf[i & 1], (i == 0) ? g_b : g_F[i - 1], g_wbuf[(i + 1) & 1],
                   &su, red);
        gbar();
    }

    // Anderson: combine -> spmm (last g() dead); final combine fuses decode.
    for (int k = 0; k < AAM; k++) {
        combine_phase(k, sa, decW, out);
        if (k < AAM - 1) {
            gbar();
            spmm_phase(AAM + k, k, 5, g_GGrow[k & 1], 0, (k < AAM - 2) ? 1 : 0,
                       g_wbuf[0], g_u, 0, &su, red);
            gbar();
        }
    }

    // tail: re-zero g_cur for the NEXT launch (last reader was spmm(k=3), behind a gbar)
    for (int i = gtid; i < N_NODES; i += NTHREADS) g_cur[i] = 0;
}

// ---------------- launch: ONE kernel ----------------
extern "C" void kernel_launch(void* const* d_in, const int* in_sizes, int n_in,
                              void* d_out, int out_size) {
    const float* x    = (const float*)d_in[0];
    const int*   ei   = (const int*)  d_in[1];
    const float* ew   = (const float*)d_in[2];
    const float* encW = (const float*)d_in[3];
    const float* encb = (const float*)d_in[4];
    const float* cayB = (const float*)d_in[5];
    const float* decW = (const float*)d_in[6];
    float* out = (float*)d_out;

    k_mega<<<GRID_BLOCKS, TPB>>>(x, ei, ew, encW, encb, cayB, decW, out);
}

// round 16
// speedup vs baseline: 1.1788x; 1.1788x over previous
#include <cuda_runtime.h>
#include <cuda_fp16.h>

#define N_NODES 10000
#define N_EDGES 320000
#define D_IN    128
#define D_HID   64
#define D_OUT   16
#define NH      (N_NODES * D_HID)
#define AAM     5
#define PAD     128                  // padded edge-row length
#define TPB         512
#define BLK_PER_SM  2
#define GRID_BLOCKS 296              // 148 SMs x 2 blocks guaranteed resident
#define WPB         (TPB / 32)       // 16
#define NWARPS      (GRID_BLOCKS * WPB)          // 4736
#define NTHREADS    (GRID_BLOCKS * TPB)
#define NODE_COST   48
#define COST_TOTAL  (N_EDGES + NODE_COST * N_NODES)

typedef unsigned long long ull;

// ---------------- device scratch ----------------
__device__ float  g_b[NH];
__device__ float  g_u[NH];                  // written only by Anderson combines
__device__ __half g_wbuf[2][NH];            // fp16 SPMM input (only gather reads it)
__device__ float  g_F[AAM][NH];
__device__ float  g_G[AAM][NH];
__device__ float  g_ThT[D_HID * D_HID];     // ThT[k*64+c] = Theta[c][k]
__device__ int    g_rowptr[N_NODES + 1];    // prefix of counts (partition only)
__device__ int    g_cur[N_NODES];           // zero at launch entry (re-zeroed at kernel tail)
__device__ __align__(16) int2 g_edge[N_NODES * PAD];   // padded edge rows
__device__ int    g_wstart[NWARPS + 1];
__device__ double g_GGbuf[2][15];
__device__ double g_GGrow[2][5];
__device__ unsigned          g_bar_cnt;
__device__ volatile unsigned g_bar_gen;

union SmemU {
    struct { float M[64][128]; float fct[64]; } th;            // 33 KB (setup)
    struct {
        ulonglong2 T[32][32];     // 16KB: {A[m][l], B[m][l]} packed Theta
        ulonglong2 s[WPB][32];    // 8KB: per-warp staged (sA, sB) / encoder x rows
        ull        s2[WPB][32];   // 4KB: third staged vector (sC) for triple mix
    } mix;                        // 28 KB
    int part[TPB];
};

// ---------------- f32x2 helpers ----------------
__device__ __forceinline__ void fma2(ull& d, ull a, ull b) {
    asm("fma.rn.f32x2 %0, %1, %2, %0;" : "+l"(d) : "l"(a), "l"(b));
}
__device__ __forceinline__ ull pack2(float2 v) {
    ull r; asm("mov.b64 %0, {%1, %2};" : "=l"(r) : "f"(v.x), "f"(v.y)); return r;
}
__device__ __forceinline__ float2 unpack2(ull v) {
    float2 r; asm("mov.b64 {%0, %1}, %2;" : "=f"(r.x), "=f"(r.y) : "l"(v)); return r;
}
__device__ __forceinline__ float2 gfma(float2 a, float w, float2 v) {
    a.x = fmaf(w, v.x, a.x); a.y = fmaf(w, v.y, a.y); return a;
}

// ---------------- software grid barrier ----------------
__device__ __forceinline__ void gbar() {
    __syncthreads();
    if (threadIdx.x == 0) {
        __threadfence();
        unsigned gen = g_bar_gen;
        if (atomicAdd(&g_bar_cnt, 1u) == GRID_BLOCKS - 1u) {
            g_bar_cnt = 0u;
            __threadfence();
            g_bar_gen = gen + 1u;
        } else {
            while (g_bar_gen == gen) { __nanosleep(32); }
        }
        __threadfence();
    }
    __syncthreads();
}

// ---------------- Cayley: Theta = (I+Om)^-1 (I-Om) ----------------
__device__ void theta_phase(const float* __restrict__ B, SmemU* su) {
    int tid = threadIdx.x;
    for (int idx = tid; idx < 64 * 64; idx += TPB) {
        int i = idx >> 6, j = idx & 63;
        float om = 0.5f * (B[i * 64 + j] - B[j * 64 + i]);
        float e  = (i == j) ? 1.f : 0.f;
        su->th.M[i][j]      = e + om;
        su->th.M[i][64 + j] = e - om;
    }
    __syncthreads();
    for (int k = 0; k < 64; k++) {
        float inv = 1.f / su->th.M[k][k];
        __syncthreads();
        for (int j = tid; j < 128; j += TPB) su->th.M[k][j] *= inv;
        __syncthreads();
        for (int r = tid; r < 64; r += TPB) su->th.fct[r] = su->th.M[r][k];
        __syncthreads();
        for (int idx = tid; idx < 64 * 128; idx += TPB) {
            int r = idx >> 7, j = idx & 127;
            if (r != k) su->th.M[r][j] -= su->th.fct[r] * su->th.M[k][j];
        }
        __syncthreads();
    }
    for (int idx = tid; idx < 64 * 64; idx += TPB) {
        int k = idx >> 6, c = idx & 63;
        g_ThT[idx] = su->th.M[c][64 + k];
    }
}

// ---------------- encoder + b/w0 (x staged through smem, coalesced) ----------------
__device__ void encode_phase(const float* __restrict__ x, const float* __restrict__ W,
                             const float* __restrict__ bias, SmemU* su) {
    int warp = threadIdx.x >> 5, cp = threadIdx.x & 31;
    int g = blockIdx.x * WPB + warp;
    const float2* __restrict__ W2 = (const float2*)W;
    float4* sx = (float4*)&su->mix.s[warp][0];   // 512B = one x row
    float2 bsv = ((const float2*)bias)[cp];
    for (int node = g; node < N_NODES; node += NWARPS) {
        sx[cp] = ((const float4*)(x + node * D_IN))[cp];
        __syncwarp();
        const float* xs = (const float*)sx;
        float2 acc = bsv;
#pragma unroll 16
        for (int k = 0; k < D_IN; k++) {
            float  xk = xs[k];
            float2 w2 = W2[k * 32 + cp];
            acc.x = fmaf(xk, w2.x, acc.x);
            acc.y = fmaf(xk, w2.y, acc.y);
        }
        __syncwarp();
        int row = node * 32 + cp;
        ((float2*)g_b)[row] = acc;
        ((__half2*)g_wbuf[0])[row] =
            __floats2half2_rn(2.f * fmaxf(acc.x, 0.f), 2.f * fmaxf(acc.y, 0.f));
    }
}

// ---------------- branch-free interleaved dual-node gather (counts multiple of 2 int4) ----
__device__ __forceinline__ void gather2(const int2* __restrict__ eg,
                                        const __half2* __restrict__ wv,
                                        int bA, int hcA, int bB, int hcB,
                                        int lane, float2& outA, float2& outB) {
    const int4* __restrict__ e4A = (const int4*)(eg + bA);
    const int4* __restrict__ e4B = (const int4*)(eg + bB);
    float2 aA0 = {0.f, 0.f}, aA1 = {0.f, 0.f};
    float2 aB0 = {0.f, 0.f}, aB1 = {0.f, 0.f};
    int hA = 0, hB = 0;
    while (hA + 2 <= hcA && hB + 2 <= hcB) {
        int4 dA0 = e4A[hA], dA1 = e4A[hA + 1];
        int4 dB0 = e4B[hB], dB1 = e4B[hB + 1];
        __half2 vA0 = wv[dA0.x * 32 + lane], vA1 = wv[dA0.z * 32 + lane];
        __half2 vA2 = wv[dA1.x * 32 + lane], vA3 = wv[dA1.z * 32 + lane];
        __half2 vB0 = wv[dB0.x * 32 + lane], vB1 = wv[dB0.z * 32 + lane];
        __half2 vB2 = wv[dB1.x * 32 + lane], vB3 = wv[dB1.z * 32 + lane];
        aA0 = gfma(aA0, __int_as_float(dA0.y), __half22float2(vA0));
        aA1 = gfma(aA1, __int_as_float(dA0.w), __half22float2(vA1));
        aA0 = gfma(aA0, __int_as_float(dA1.y), __half22float2(vA2));
        aA1 = gfma(aA1, __int_as_float(dA1.w), __half22float2(vA3));
        aB0 = gfma(aB0, __int_as_float(dB0.y), __half22float2(vB0));
        aB1 = gfma(aB1, __int_as_float(dB0.w), __half22float2(vB1));
        aB0 = gfma(aB0, __int_as_float(dB1.y), __half22float2(vB2));
        aB1 = gfma(aB1, __int_as_float(dB1.w), __half22float2(vB3));
        hA += 2; hB += 2;
    }
    for (; hA + 2 <= hcA; hA += 2) {
        int4 d0 = e4A[hA], d1 = e4A[hA + 1];
        __half2 v0 = wv[d0.x * 32 + lane], v1 = wv[d0.z * 32 + lane];
        __half2 v2 = wv[d1.x * 32 + lane], v3 = wv[d1.z * 32 + lane];
        aA0 = gfma(aA0, __int_as_float(d0.y), __half22float2(v0));
        aA1 = gfma(aA1, __int_as_float(d0.w), __half22float2(v1));
        aA0 = gfma(aA0, __int_as_float(d1.y), __half22float2(v2));
        aA1 = gfma(aA1, __int_as_float(d1.w), __half22float2(v3));
    }
    for (; hB + 2 <= hcB; hB += 2) {
        int4 d0 = e4B[hB], d1 = e4B[hB + 1];
        __half2 v0 = wv[d0.x * 32 + lane], v1 = wv[d0.z * 32 + lane];
        __half2 v2 = wv[d1.x * 32 + lane], v3 = wv[d1.z * 32 + lane];
        aB0 = gfma(aB0, __int_as_float(d0.y), __half22float2(v0));
        aB1 = gfma(aB1, __int_as_float(d0.w), __half22float2(v1));
        aB0 = gfma(aB0, __int_as_float(d1.y), __half22float2(v2));
        aB1 = gfma(aB1, __int_as_float(d1.w), __half22float2(v3));
    }
    outA = make_float2(aA0.x + aA1.x, aA0.y + aA1.y);
    outB = make_float2(aB0.x + aB1.x, aB0.y + aB1.y);
}

// ---------------- triple-node interleaved gather ----------------
__device__ __forceinline__ void gather3(const int2* __restrict__ eg,
                                        const __half2* __restrict__ wv,
                                        int bA, int hcA, int bB, int hcB,
                                        int bC, int hcC, int lane,
                                        float2& outA, float2& outB, float2& outC) {
    const int4* __restrict__ e4A = (const int4*)(eg + bA);
    const int4* __restrict__ e4B = (const int4*)(eg + bB);
    const int4* __restrict__ e4C = (const int4*)(eg + bC);
    float2 aA0 = {0.f, 0.f}, aA1 = {0.f, 0.f};
    float2 aB0 = {0.f, 0.f}, aB1 = {0.f, 0.f};
    float2 aC0 = {0.f, 0.f}, aC1 = {0.f, 0.f};
    int hA = 0, hB = 0, hC = 0;
    while (hA + 2 <= hcA && hB + 2 <= hcB && hC + 2 <= hcC) {
        int4 dA0 = e4A[hA], dA1 = e4A[hA + 1];
        int4 dB0 = e4B[hB], dB1 = e4B[hB + 1];
        int4 dC0 = e4C[hC], dC1 = e4C[hC + 1];
        __half2 vA0 = wv[dA0.x * 32 + lane], vA1 = wv[dA0.z * 32 + lane];
        __half2 vA2 = wv[dA1.x * 32 + lane], vA3 = wv[dA1.z * 32 + lane];
        __half2 vB0 = wv[dB0.x * 32 + lane], vB1 = wv[dB0.z * 32 + lane];
        __half2 vB2 = wv[dB1.x * 32 + lane], vB3 = wv[dB1.z * 32 + lane];
        __half2 vC0 = wv[dC0.x * 32 + lane], vC1 = wv[dC0.z * 32 + lane];
        __half2 vC2 = wv[dC1.x * 32 + lane], vC3 = wv[dC1.z * 32 + lane];
        aA0 = gfma(aA0, __int_as_float(dA0.y), __half22float2(vA0));
        aA1 = gfma(aA1, __int_as_float(dA0.w), __half22float2(vA1));
        aA0 = gfma(aA0, __int_as_float(dA1.y), __half22float2(vA2));
        aA1 = gfma(aA1, __int_as_float(dA1.w), __half22float2(vA3));
        aB0 = gfma(aB0, __int_as_float(dB0.y), __half22float2(vB0));
        aB1 = gfma(aB1, __int_as_float(dB0.w), __half22float2(vB1));
        aB0 = gfma(aB0, __int_as_float(dB1.y), __half22float2(vB2));
        aB1 = gfma(aB1, __int_as_float(dB1.w), __half22float2(vB3));
        aC0 = gfma(aC0, __int_as_float(dC0.y), __half22float2(vC0));
        aC1 = gfma(aC1, __int_as_float(dC0.w), __half22float2(vC1));
        aC0 = gfma(aC0, __int_as_float(dC1.y), __half22float2(vC2));
        aC1 = gfma(aC1, __int_as_float(dC1.w), __half22float2(vC3));
        hA += 2; hB += 2; hC += 2;
    }
    for (; hA + 2 <= hcA; hA += 2) {
        int4 d0 = e4A[hA], d1 = e4A[hA + 1];
        __half2 v0 = wv[d0.x * 32 + lane], v1 = wv[d0.z * 32 + lane];
        __half2 v2 = wv[d1.x * 32 + lane], v3 = wv[d1.z * 32 + lane];
        aA0 = gfma(aA0, __int_as_float(d0.y), __half22float2(v0));
        aA1 = gfma(aA1, __int_as_float(d0.w), __half22float2(v1));
        aA0 = gfma(aA0, __int_as_float(d1.y), __half22float2(v2));
        aA1 = gfma(aA1, __int_as_float(d1.w), __half22float2(v3));
    }
    for (; hB + 2 <= hcB; hB += 2) {
        int4 d0 = e4B[hB], d1 = e4B[hB + 1];
        __half2 v0 = wv[d0.x * 32 + lane], v1 = wv[d0.z * 32 + lane];
        __half2 v2 = wv[d1.x * 32 + lane], v3 = wv[d1.z * 32 + lane];
        aB0 = gfma(aB0, __int_as_float(d0.y), __half22float2(v0));
        aB1 = gfma(aB1, __int_as_float(d0.w), __half22float2(v1));
        aB0 = gfma(aB0, __int_as_float(d1.y), __half22float2(v2));
        aB1 = gfma(aB1, __int_as_float(d1.w), __half22float2(v3));
    }
    for (; hC + 2 <= hcC; hC += 2) {
        int4 d0 = e4C[hC], d1 = e4C[hC + 1];
        __half2 v0 = wv[d0.x * 32 + lane], v1 = wv[d0.z * 32 + lane];
        __half2 v2 = wv[d1.x * 32 + lane], v3 = wv[d1.z * 32 + lane];
        aC0 = gfma(aC0, __int_as_float(d0.y), __half22float2(v0));
        aC1 = gfma(aC1, __int_as_float(d0.w), __half22float2(v1));
        aC0 = gfma(aC0, __int_as_float(d1.y), __half22float2(v2));
        aC1 = gfma(aC1, __int_as_float(d1.w), __half22float2(v3));
    }
    outA = make_float2(aA0.x + aA1.x, aA0.y + aA1.y);
    outB = make_float2(aB0.x + aB1.x, aB0.y + aB1.y);
    outC = make_float2(aC0.x + aC1.x, aC0.y + aC1.y);
}

// ---------------- per-node epilogue ----------------
__device__ __forceinline__ void epilogue(int node, int lane, float2 mix, int slot,
                                         int npairs, int wr_next, int wr_g,
                                         const float* __restrict__ usrc,
                                         __half* __restrict__ wdst, float* p) {
    int row = node * 32 + lane;
    float2 bb = ((const float2*)g_b)[row];
    float2 uu = ((const float2*)usrc)[row];
    float2 val = make_float2(bb.x + 0.5f * mix.x, bb.y + 0.5f * mix.y);
    ((float2*)g_F[slot])[row] = val;
    float2 gn = make_float2(val.x - uu.x, val.y - uu.y);
    if (wr_g) ((float2*)g_G[slot])[row] = gn;
    if (wr_next) {
        ((__half2*)wdst)[row] =
            __floats2half2_rn(2.f * fmaxf(val.x, 0.f) - val.x + bb.x,
                              2.f * fmaxf(val.y, 0.f) - val.y + bb.y);
    }
    for (int j = 0; j < npairs; ++j) {
        float2 gj = (j == slot) ? gn : ((const float2*)g_G[j])[row];
        p[j] = fmaf(gn.x, gj.x, fmaf(gn.y, gj.y, p[j]));
    }
}

// ---------------- fused SPMM + LDS.128 mix + G + Gram partials ----------------
__device__ void spmm_phase(int slot, int npairs, double* target, int wr_next, int wr_g,
                           const __half* __restrict__ wsrc,
                           const float* __restrict__ usrc,
                           __half* __restrict__ wdst,
                           SmemU* su, double (*red)[5]) {
    int warp = threadIdx.x >> 5, lane = threadIdx.x & 31;
    int w = blockIdx.x * WPB + warp;
    const int2*    __restrict__ eg = g_edge;
    const __half2* __restrict__ wv = (const __half2*)wsrc;
    float p[5];
#pragma unroll
    for (int j = 0; j < 5; j++) p[j] = 0.f;

    int n = g_wstart[w], ne = g_wstart[w + 1];
    int cnt = ne - n;

    // triple path: odd counts >= 3 take one batched triple first (one mix, one T sweep)
    if ((cnt & 1) && cnt >= 3) {
        int hcA = ((g_cur[n] + 3) & ~3) >> 1;
        int hcB = ((g_cur[n + 1] + 3) & ~3) >> 1;
        int hcC = ((g_cur[n + 2] + 3) & ~3) >> 1;
        float2 accA, accB, accC;
        gather3(eg, wv, n * PAD, hcA, (n + 1) * PAD, hcB, (n + 2) * PAD, hcC,
                lane, accA, accB, accC);
        __syncwarp();
        su->mix.s[warp][lane]  = make_ulonglong2(pack2(accA), pack2(accB));
        su->mix.s2[warp][lane] = pack2(accC);
        __syncwarp();
        ull PA = 0ull, QA = 0ull, PB = 0ull, QB = 0ull, PC = 0ull, QC = 0ull;
#pragma unroll
        for (int m = 0; m < 32; ++m) {
            ulonglong2 sp = su->mix.s[warp][m];
            ull spC       = su->mix.s2[warp][m];
            ulonglong2 T  = su->mix.T[m][lane];
            fma2(PA, T.x, sp.x); fma2(QA, T.y, sp.x);
            fma2(PB, T.x, sp.y); fma2(QB, T.y, sp.y);
            fma2(PC, T.x, spC);  fma2(QC, T.y, spC);
        }
        float2 pA = unpack2(PA), qA = unpack2(QA);
        float2 pB = unpack2(PB), qB = unpack2(QB);
        float2 pC = unpack2(PC), qC = unpack2(QC);
        epilogue(n,     lane, make_float2(pA.x + pA.y, qA.x + qA.y),
                 slot, npairs, wr_next, wr_g, usrc, wdst, p);
        epilogue(n + 1, lane, make_float2(pB.x + pB.y, qB.x + qB.y),
                 slot, npairs, wr_next, wr_g, usrc, wdst, p);
        epilogue(n + 2, lane, make_float2(pC.x + pC.y, qC.x + qC.y),
                 slot, npairs, wr_next, wr_g, usrc, wdst, p);
        n += 3;
    }

    // pairs
    for (; n + 1 < ne; n += 2) {
        int hcA = ((g_cur[n] + 3) & ~3) >> 1;
        int hcB = ((g_cur[n + 1] + 3) & ~3) >> 1;
        float2 accA, accB;
        gather2(eg, wv, n * PAD, hcA, (n + 1) * PAD, hcB, lane, accA, accB);
        __syncwarp();
        su->mix.s[warp][lane] = make_ulonglong2(pack2(accA), pack2(accB));
        __syncwarp();
        ull PA = 0ull, QA = 0ull, PB = 0ull, QB = 0ull;
#pragma unroll
        for (int m = 0; m < 32; ++m) {
            ulonglong2 sp = su->mix.s[warp][m];   // broadcast LDS.128
            ulonglong2 T  = su->mix.T[m][lane];   // conflict-free LDS.128
            fma2(PA, T.x, sp.x); fma2(QA, T.y, sp.x);
            fma2(PB, T.x, sp.y); fma2(QB, T.y, sp.y);
        }
        float2 pA = unpack2(PA), qA = unpack2(QA);
        float2 pB = unpack2(PB), qB = unpack2(QB);
        epilogue(n,     lane, make_float2(pA.x + pA.y, qA.x + qA.y),
                 slot, npairs, wr_next, wr_g, usrc, wdst, p);
        epilogue(n + 1, lane, make_float2(pB.x + pB.y, qB.x + qB.y),
                 slot, npairs, wr_next, wr_g, usrc, wdst, p);
    }
    // single (only when warp owns exactly 1 node)
    if (n < ne) {
        int hcA = ((g_cur[n] + 3) & ~3) >> 1;
        float2 acc, dummy;
        gather2(eg, wv, n * PAD, hcA, n * PAD, 0, lane, acc, dummy);
        __syncwarp();
        su->mix.s[warp][lane] = make_ulonglong2(pack2(acc), 0ull);
        __syncwarp();
        ull PA = 0ull, QA = 0ull;
#pragma unroll
        for (int m = 0; m < 32; ++m) {
            ulonglong2 sp = su->mix.s[warp][m];
            ulonglong2 T  = su->mix.T[m][lane];
            fma2(PA, T.x, sp.x);
            fma2(QA, T.y, sp.x);
        }
        float2 pA = unpack2(PA), qA = unpack2(QA);
        epilogue(n, lane, make_float2(pA.x + pA.y, qA.x + qA.y),
                 slot, npairs, wr_next, wr_g, usrc, wdst, p);
    }

#pragma unroll
    for (int j = 0; j < 5; ++j)
        for (int off = 16; off > 0; off >>= 1)
            p[j] += __shfl_down_sync(0xffffffffu, p[j], off);
    __syncthreads();
    if (lane == 0)
        for (int j = 0; j < 5; ++j) red[warp][j] = (double)p[j];
    __syncthreads();
    if (threadIdx.x < npairs) {
        int j = threadIdx.x;
        double s = 0.0;
        for (int ww = 0; ww < WPB; ww++) s += red[ww][j];
        atomicAdd(&target[j], s);
    }
}

// ---------------- combine(k): Gram merge + 5x5 solve + u_new (+ fused decode at k=4) ----------------
__device__ void combine_phase(int k, float* sa, const float* __restrict__ decW,
                              float* __restrict__ out) {
    if (threadIdx.x == 0) {
        double M[5][5];
        const double* base = g_GGbuf[k & 1];
        int c = 0;
        for (int i = 0; i < 5; i++)
            for (int j = 0; j <= i; j++) { M[i][j] = base[c]; M[j][i] = base[c]; c++; }
        if (k > 0) {
            int idx = k - 1;
            const double* row = g_GGrow[(k - 1) & 1];
            for (int j = 0; j < 5; j++) { M[idx][j] = row[j]; M[j][idx] = row[j]; }
        }
        if (blockIdx.x == 0 && k < AAM - 1) {
            c = 0;
            for (int i = 0; i < 5; i++)
                for (int j = 0; j <= i; j++) g_GGbuf[(k + 1) & 1][c++] = M[i][j];
            for (int j = 0; j < 5; j++) g_GGrow[k & 1][j] = 0.0;
        }
        float A[5][6];
        for (int i = 0; i < 5; i++) {
            for (int j = 0; j < 5; j++) A[i][j] = (float)M[i][j];
            A[i][i] += 1e-4f;
            A[i][5] = 1.f;
        }
        for (int kk = 0; kk < 5; kk++) {
            int piv = kk; float mx = fabsf(A[kk][kk]);
            for (int r = kk + 1; r < 5; r++)
                if (fabsf(A[r][kk]) > mx) { mx = fabsf(A[r][kk]); piv = r; }
            if (piv != kk)
                for (int j = 0; j < 6; j++) { float t = A[kk][j]; A[kk][j] = A[piv][j]; A[piv][j] = t; }
            float inv = 1.f / A[kk][kk];
            for (int r = kk + 1; r < 5; r++) {
                float f = A[r][kk] * inv;
                for (int j = kk; j < 6; j++) A[r][j] -= f * A[kk][j];
            }
        }
        float a[5];
        for (int kk = 4; kk >= 0; kk--) {
            float s = A[kk][5];
            for (int j = kk + 1; j < 5; j++) s -= A[kk][j] * a[j];
            a[kk] = s / A[kk][kk];
        }
        float sum = a[0] + a[1] + a[2] + a[3] + a[4];
        for (int j = 0; j < 5; j++) sa[j] = a[j] / sum;
    }
    __syncthreads();
    float a0 = sa[0], a1 = sa[1], a2 = sa[2], a3 = sa[3], a4 = sa[4];

    int warp = threadIdx.x >> 5, lane = threadIdx.x & 31;
    int g = blockIdx.x * WPB + warp;
    const float2* F0 = (const float2*)g_F[0];
    const float2* F1 = (const float2*)g_F[1];
    const float2* F2 = (const float2*)g_F[2];
    const float2* F3 = (const float2*)g_F[3];
    const float2* F4 = (const float2*)g_F[4];
    for (int node = g; node < N_NODES; node += NWARPS) {
        int idx = node * 32 + lane;
        float2 f0 = F0[idx], f1 = F1[idx], f2 = F2[idx], f3 = F3[idx], f4 = F4[idx];
        float2 un;
        un.x = a0 * f0.x + a1 * f1.x + a2 * f2.x + a3 * f3.x + a4 * f4.x;
        un.y = a0 * f0.y + a1 * f1.y + a2 * f2.y + a3 * f3.y + a4 * f4.y;
        if (k < AAM - 1) {
            ((float2*)g_u)[idx] = un;
            float2 bb = ((const float2*)g_b)[idx];
            ((__half2*)g_wbuf[0])[idx] =
                __floats2half2_rn(2.f * fmaxf(un.x, 0.f) - un.x + bb.x,
                                  2.f * fmaxf(un.y, 0.f) - un.y + bb.y);
        } else {
            float rx = fmaxf(un.x, 0.f), ry = fmaxf(un.y, 0.f);
            int o = lane & 15, half = lane >> 4;
            float acc = 0.f;
#pragma unroll
            for (int i = 0; i < 16; i++) {
                int m = half * 16 + i;
                float sx = __shfl_sync(0xffffffffu, rx, m);
                float sy = __shfl_sync(0xffffffffu, ry, m);
                acc = fmaf(sx, decW[(2 * m) * 16 + o], acc);
                acc = fmaf(sy, decW[(2 * m + 1) * 16 + o], acc);
            }
            acc += __shfl_down_sync(0xffffffffu, acc, 16);
            if (half == 0) out[node * 16 + o] = acc;
        }
    }
}

// ---------------- the single persistent kernel ----------------
__global__ void __launch_bounds__(TPB, BLK_PER_SM) k_mega(
    const float* __restrict__ x, const int* __restrict__ ei,
    const float* __restrict__ ew, const float* __restrict__ encW,
    const float* __restrict__ encb, const float* __restrict__ cayB,
    const float* __restrict__ decW, float* __restrict__ out)
{
    __shared__ SmemU su;
    __shared__ double red[WPB][5];
    __shared__ float sa[5];

    const int* src = ei;
    const int* dst = ei + N_EDGES;
    int gtid = blockIdx.x * TPB + threadIdx.x;

    // Phase 1: one-pass padded-row scatter (g_cur pre-zeroed) || encoder || zero GGbuf[0]
    for (int e = gtid; e < N_EDGES; e += NTHREADS) {
        int d = dst[e];
        int pos = atomicAdd(&g_cur[d], 1);
        g_edge[d * PAD + pos] = make_int2(src[e], __float_as_int(ew[e]));
    }
    if (gtid < 15) g_GGbuf[0][gtid] = 0.0;
    encode_phase(x, encW, encb, &su);
    gbar();

    // Phase 2: count-prefix scan (block 0) || Cayley theta (block 1)
    //          || zero-fill row padding to multiple of 4 edges (blocks >= 2)
    if (blockIdx.x == 0) {
        int t = threadIdx.x;
        const int CH = (N_NODES + TPB - 1) / TPB;   // 20
        int beg = t * CH, end = beg + CH; if (end > N_NODES) end = N_NODES;
        int s = 0;
        for (int i = beg; i < end; i++) s += g_cur[i];
        su.part[t] = s;
        __syncthreads();
        for (int d = 1; d < TPB; d <<= 1) {
            int v = (t >= d) ? su.part[t - d] : 0;
            __syncthreads();
            su.part[t] += v;
            __syncthreads();
        }
        int off = (t > 0) ? su.part[t - 1] : 0;
        for (int i = beg; i < end; i++) {
            g_rowptr[i] = off;
            off += g_cur[i];
        }
        if (t == 0) g_rowptr[N_NODES] = N_EDGES;
    } else if (blockIdx.x == 1) {
        theta_phase(cayB, &su);
    } else {
        int base = (blockIdx.x - 2) * TPB + threadIdx.x;
        for (int i = base; i < N_NODES; i += (GRID_BLOCKS - 2) * TPB) {
            int c = g_cur[i];
            int cr = (c + 3) & ~3;
            for (int e = c; e < cr; e++)
                g_edge[i * PAD + e] = make_int2(0, 0);   // w = 0.0f
        }
    }
    gbar();

    // Phase 3: balanced warp partition || stage packed Theta
    if (gtid <= NWARPS) {
        if (gtid == NWARPS) {
            g_wstart[NWARPS] = N_NODES;
        } else {
            long long target = (long long)gtid * COST_TOTAL / NWARPS;
            int lo = 0, hi = N_NODES;
            while (lo < hi) {
                int mid = (lo + hi) >> 1;
                long long c = (long long)g_rowptr[mid] + (long long)NODE_COST * mid;
                if (c < target) lo = mid + 1; else hi = mid;
            }
            g_wstart[gtid] = lo;
        }
    }
    for (int i = threadIdx.x; i < 1024; i += TPB) {
        int m = i >> 5, l = i & 31;
        float a0 = g_ThT[(2 * m) * 64 + 2 * l];
        float a1 = g_ThT[(2 * m + 1) * 64 + 2 * l];
        float b0 = g_ThT[(2 * m) * 64 + 2 * l + 1];
        float b1 = g_ThT[(2 * m + 1) * 64 + 2 * l + 1];
        su.mix.T[m][l] = make_ulonglong2(pack2(make_float2(a0, a1)),
                                         pack2(make_float2(b0, b1)));
    }
    gbar();

    // history: 5 PR sweeps (w ping-pong); uu read from b / F[i-1]
    for (int i = 0; i < AAM; i++) {
        spmm_phase(i, i + 1, &g_GGbuf[0][i * (i + 1) / 2], (i < AAM - 1) ? 1 : 0, 1,
                   g_wbuf[i & 1], (i == 0) ? g_b : g_F[i - 1], g_wbuf[(i + 1) & 1],
                   &su, red);
        gbar();
    }

    // Anderson: combine -> spmm (last g() dead); final combine fuses decode.
    for (int k = 0; k < AAM; k++) {
        combine_phase(k, sa, decW, out);
        if (k < AAM - 1) {
            gbar();
            spmm_phase(k, 5, g_GGrow[k & 1], 0, (k < AAM - 2) ? 1 : 0,
                       g_wbuf[0], g_u, 0, &su, red);
            gbar();
        }
    }

    // tail: re-zero g_cur for the NEXT launch (last reader was spmm(k=3), behind a gbar)
    for (int i = gtid; i < N_NODES; i += NTHREADS) g_cur[i] = 0;
}

// ---------------- launch: ONE kernel ----------------
extern "C" void kernel_launch(void* const* d_in, const int* in_sizes, int n_in,
                              void* d_out, int out_size) {
    const float* x    = (const float*)d_in[0];
    const int*   ei   = (const int*)  d_in[1];
    const float* ew   = (const float*)d_in[2];
    const float* encW = (const float*)d_in[3];
    const float* encb = (const float*)d_in[4];
    const float* cayB = (const float*)d_in[5];
    const float* decW = (const float*)d_in[6];
    float* out = (float*)d_out;

    k_mega<<<GRID_BLOCKS, TPB>>>(x, ei, ew, encW, encb, cayB, decW, out);
}

// round 17
// speedup vs baseline: 1.2176x; 1.0329x over previous
#include <cuda_runtime.h>
#include <cuda_fp16.h>

#define N_NODES 10000
#define N_EDGES 320000
#define D_IN    128
#define D_HID   64
#define D_OUT   16
#define NH      (N_NODES * D_HID)
#define AAM     5
#define PAD     128                  // padded edge-row length (edges)
#define TPB         512
#define BLK_PER_SM  2
#define GRID_BLOCKS 296              // 148 SMs x 2 blocks guaranteed resident
#define WPB         (TPB / 32)       // 16
#define NWARPS      (GRID_BLOCKS * WPB)          // 4736
#define NTHREADS    (GRID_BLOCKS * TPB)
#define NODE_COST   48
#define COST_TOTAL  (N_EDGES + NODE_COST * N_NODES)

typedef unsigned long long ull;
typedef unsigned int uint;

// ---------------- device scratch ----------------
__device__ float  g_b[NH];
__device__ float  g_u[NH];                  // written only by Anderson combines
__device__ __half g_wbuf[2][NH];            // fp16 SPMM input (only gather reads it)
__device__ float  g_F[AAM][NH];
__device__ float  g_G[AAM][NH];
__device__ float  g_ThT[D_HID * D_HID];     // ThT[k*64+c] = Theta[c][k]
__device__ int    g_rowptr[N_NODES + 1];    // prefix of counts (partition only)
__device__ int    g_cur[N_NODES];           // zero at launch entry (re-zeroed at kernel tail)
__device__ __align__(16) uint g_edge[N_NODES * PAD];  // packed edges: src(16b) | half_w(16b)
__device__ int    g_wstart[NWARPS + 1];
__device__ double g_GGbuf[2][15];
__device__ double g_GGrow[2][5];
__device__ unsigned          g_bar_cnt;
__device__ volatile unsigned g_bar_gen;

union SmemU {
    struct { float M[64][128]; float fct[64]; } th;            // 33 KB (setup)
    struct {
        ulonglong2 T[32][32];     // 16KB: {A[m][l], B[m][l]} packed Theta
        ulonglong2 s[WPB][32];    // 8KB: per-warp staged (sA, sB) / encoder x rows
        ull        s2[WPB][32];   // 4KB: third staged vector (sC) for triple mix
    } mix;                        // 28 KB
    int part[TPB];
};

// ---------------- helpers ----------------
__device__ __forceinline__ void fma2(ull& d, ull a, ull b) {
    asm("fma.rn.f32x2 %0, %1, %2, %0;" : "+l"(d) : "l"(a), "l"(b));
}
__device__ __forceinline__ ull pack2(float2 v) {
    ull r; asm("mov.b64 %0, {%1, %2};" : "=l"(r) : "f"(v.x), "f"(v.y)); return r;
}
__device__ __forceinline__ float2 unpack2(ull v) {
    float2 r; asm("mov.b64 {%0, %1}, %2;" : "=f"(r.x), "=f"(r.y) : "l"(v)); return r;
}
__device__ __forceinline__ float2 gfma(float2 a, float w, float2 v) {
    a.x = fmaf(w, v.x, a.x); a.y = fmaf(w, v.y, a.y); return a;
}
__device__ __forceinline__ float ew16(uint d) {     // decode fp16 weight from high 16 bits
    return __half2float(__ushort_as_half((unsigned short)(d >> 16)));
}

// ---------------- software grid barrier ----------------
__device__ __forceinline__ void gbar() {
    __syncthreads();
    if (threadIdx.x == 0) {
        __threadfence();
        unsigned gen = g_bar_gen;
        if (atomicAdd(&g_bar_cnt, 1u) == GRID_BLOCKS - 1u) {
            g_bar_cnt = 0u;
            __threadfence();
            g_bar_gen = gen + 1u;
        } else {
            while (g_bar_gen == gen) { __nanosleep(32); }
        }
        __threadfence();
    }
    __syncthreads();
}

// ---------------- Cayley: Theta = (I+Om)^-1 (I-Om) ----------------
__device__ void theta_phase(const float* __restrict__ B, SmemU* su) {
    int tid = threadIdx.x;
    for (int idx = tid; idx < 64 * 64; idx += TPB) {
        int i = idx >> 6, j = idx & 63;
        float om = 0.5f * (B[i * 64 + j] - B[j * 64 + i]);
        float e  = (i == j) ? 1.f : 0.f;
        su->th.M[i][j]      = e + om;
        su->th.M[i][64 + j] = e - om;
    }
    __syncthreads();
    for (int k = 0; k < 64; k++) {
        float inv = 1.f / su->th.M[k][k];
        __syncthreads();
        for (int j = tid; j < 128; j += TPB) su->th.M[k][j] *= inv;
        __syncthreads();
        for (int r = tid; r < 64; r += TPB) su->th.fct[r] = su->th.M[r][k];
        __syncthreads();
        for (int idx = tid; idx < 64 * 128; idx += TPB) {
            int r = idx >> 7, j = idx & 127;
            if (r != k) su->th.M[r][j] -= su->th.fct[r] * su->th.M[k][j];
        }
        __syncthreads();
    }
    for (int idx = tid; idx < 64 * 64; idx += TPB) {
        int k = idx >> 6, c = idx & 63;
        g_ThT[idx] = su->th.M[c][64 + k];
    }
}

// ---------------- encoder + b/w0 (x staged through smem, coalesced) ----------------
__device__ void encode_phase(const float* __restrict__ x, const float* __restrict__ W,
                             const float* __restrict__ bias, SmemU* su) {
    int warp = threadIdx.x >> 5, cp = threadIdx.x & 31;
    int g = blockIdx.x * WPB + warp;
    const float2* __restrict__ W2 = (const float2*)W;
    float4* sx = (float4*)&su->mix.s[warp][0];   // 512B = one x row
    float2 bsv = ((const float2*)bias)[cp];
    for (int node = g; node < N_NODES; node += NWARPS) {
        sx[cp] = ((const float4*)(x + node * D_IN))[cp];
        __syncwarp();
        const float* xs = (const float*)sx;
        float2 acc = bsv;
#pragma unroll 16
        for (int k = 0; k < D_IN; k++) {
            float  xk = xs[k];
            float2 w2 = W2[k * 32 + cp];
            acc.x = fmaf(xk, w2.x, acc.x);
            acc.y = fmaf(xk, w2.y, acc.y);
        }
        __syncwarp();
        int row = node * 32 + cp;
        ((float2*)g_b)[row] = acc;
        ((__half2*)g_wbuf[0])[row] =
            __floats2half2_rn(2.f * fmaxf(acc.x, 0.f), 2.f * fmaxf(acc.y, 0.f));
    }
}

// ---------------- dual-node gather: 4-byte packed edges, uint4 = 4 edges ----------------
__device__ __forceinline__ void gather2(const uint* __restrict__ eg,
                                        const __half2* __restrict__ wv,
                                        int bA, int qcA, int bB, int qcB,
                                        int lane, float2& outA, float2& outB) {
    const uint4* __restrict__ e4A = (const uint4*)(eg + bA);
    const uint4* __restrict__ e4B = (const uint4*)(eg + bB);
    float2 aA0 = {0.f, 0.f}, aA1 = {0.f, 0.f};
    float2 aB0 = {0.f, 0.f}, aB1 = {0.f, 0.f};
    int qA = 0, qB = 0;
    while (qA < qcA && qB < qcB) {           // 8 edges / iter, 2 desc LDG.128
        uint4 dA = e4A[qA], dB = e4B[qB];
        __half2 vA0 = wv[(dA.x & 0xFFFF) * 32 + lane];
        __half2 vA1 = wv[(dA.y & 0xFFFF) * 32 + lane];
        __half2 vA2 = wv[(dA.z & 0xFFFF) * 32 + lane];
        __half2 vA3 = wv[(dA.w & 0xFFFF) * 32 + lane];
        __half2 vB0 = wv[(dB.x & 0xFFFF) * 32 + lane];
        __half2 vB1 = wv[(dB.y & 0xFFFF) * 32 + lane];
        __half2 vB2 = wv[(dB.z & 0xFFFF) * 32 + lane];
        __half2 vB3 = wv[(dB.w & 0xFFFF) * 32 + lane];
        aA0 = gfma(aA0, ew16(dA.x), __half22float2(vA0));
        aA1 = gfma(aA1, ew16(dA.y), __half22float2(vA1));
        aA0 = gfma(aA0, ew16(dA.z), __half22float2(vA2));
        aA1 = gfma(aA1, ew16(dA.w), __half22float2(vA3));
        aB0 = gfma(aB0, ew16(dB.x), __half22float2(vB0));
        aB1 = gfma(aB1, ew16(dB.y), __half22float2(vB1));
        aB0 = gfma(aB0, ew16(dB.z), __half22float2(vB2));
        aB1 = gfma(aB1, ew16(dB.w), __half22float2(vB3));
        qA++; qB++;
    }
    for (; qA < qcA; qA++) {
        uint4 d = e4A[qA];
        __half2 v0 = wv[(d.x & 0xFFFF) * 32 + lane];
        __half2 v1 = wv[(d.y & 0xFFFF) * 32 + lane];
        __half2 v2 = wv[(d.z & 0xFFFF) * 32 + lane];
        __half2 v3 = wv[(d.w & 0xFFFF) * 32 + lane];
        aA0 = gfma(aA0, ew16(d.x), __half22float2(v0));
        aA1 = gfma(aA1, ew16(d.y), __half22float2(v1));
        aA0 = gfma(aA0, ew16(d.z), __half22float2(v2));
        aA1 = gfma(aA1, ew16(d.w), __half22float2(v3));
    }
    for (; qB < qcB; qB++) {
        uint4 d = e4B[qB];
        __half2 v0 = wv[(d.x & 0xFFFF) * 32 + lane];
        __half2 v1 = wv[(d.y & 0xFFFF) * 32 + lane];
        __half2 v2 = wv[(d.z & 0xFFFF) * 32 + lane];
        __half2 v3 = wv[(d.w & 0xFFFF) * 32 + lane];
        aB0 = gfma(aB0, ew16(d.x), __half22float2(v0));
        aB1 = gfma(aB1, ew16(d.y), __half22float2(v1));
        aB0 = gfma(aB0, ew16(d.z), __half22float2(v2));
        aB1 = gfma(aB1, ew16(d.w), __half22float2(v3));
    }
    outA = make_float2(aA0.x + aA1.x, aA0.y + aA1.y);
    outB = make_float2(aB0.x + aB1.x, aB0.y + aB1.y);
}

// ---------------- triple-node gather ----------------
__device__ __forceinline__ void gather3(const uint* __restrict__ eg,
                                        const __half2* __restrict__ wv,
                                        int bA, int qcA, int bB, int qcB,
                                        int bC, int qcC, int lane,
                                        float2& outA, float2& outB, float2& outC) {
    const uint4* __restrict__ e4C = (const uint4*)(eg + bC);
    float2 aC0 = {0.f, 0.f}, aC1 = {0.f, 0.f};
    gather2(eg, wv, bA, qcA, bB, qcB, lane, outA, outB);
    for (int q = 0; q < qcC; q++) {
        uint4 d = e4C[q];
        __half2 v0 = wv[(d.x & 0xFFFF) * 32 + lane];
        __half2 v1 = wv[(d.y & 0xFFFF) * 32 + lane];
        __half2 v2 = wv[(d.z & 0xFFFF) * 32 + lane];
        __half2 v3 = wv[(d.w & 0xFFFF) * 32 + lane];
        aC0 = gfma(aC0, ew16(d.x), __half22float2(v0));
        aC1 = gfma(aC1, ew16(d.y), __half22float2(v1));
        aC0 = gfma(aC0, ew16(d.z), __half22float2(v2));
        aC1 = gfma(aC1, ew16(d.w), __half22float2(v3));
    }
    outC = make_float2(aC0.x + aC1.x, aC0.y + aC1.y);
}

// ---------------- per-node epilogue (bb/uu preloaded by caller) ----------------
__device__ __forceinline__ void epilogue(int node, int lane, float2 mix, int slot,
                                         int npairs, int wr_next, int wr_g,
                                         float2 bb, float2 uu,
                                         __half* __restrict__ wdst, float* p) {
    int row = node * 32 + lane;
    float2 val = make_float2(bb.x + 0.5f * mix.x, bb.y + 0.5f * mix.y);
    ((float2*)g_F[slot])[row] = val;
    float2 gn = make_float2(val.x - uu.x, val.y - uu.y);
    if (wr_g) ((float2*)g_G[slot])[row] = gn;
    if (wr_next) {
        ((__half2*)wdst)[row] =
            __floats2half2_rn(2.f * fmaxf(val.x, 0.f) - val.x + bb.x,
                              2.f * fmaxf(val.y, 0.f) - val.y + bb.y);
    }
    for (int j = 0; j < npairs; ++j) {
        float2 gj = (j == slot) ? gn : ((const float2*)g_G[j])[row];
        p[j] = fmaf(gn.x, gj.x, fmaf(gn.y, gj.y, p[j]));
    }
}

// ---------------- fused SPMM + LDS.128 mix + G + Gram partials ----------------
__device__ void spmm_phase(int slot, int npairs, double* target, int wr_next, int wr_g,
                           const __half* __restrict__ wsrc,
                           const float* __restrict__ usrc,
                           __half* __restrict__ wdst,
                           SmemU* su, double (*red)[5]) {
    int warp = threadIdx.x >> 5, lane = threadIdx.x & 31;
    int w = blockIdx.x * WPB + warp;
    const uint*    __restrict__ eg = g_edge;
    const __half2* __restrict__ wv = (const __half2*)wsrc;
    float p[5];
#pragma unroll
    for (int j = 0; j < 5; j++) p[j] = 0.f;

    int n = g_wstart[w], ne = g_wstart[w + 1];
    int cnt = ne - n;

    // triple path: odd counts >= 3 batched (one mix, one T sweep)
    if ((cnt & 1) && cnt >= 3) {
        int qcA = (g_cur[n] + 3) >> 2;
        int qcB = (g_cur[n + 1] + 3) >> 2;
        int qcC = (g_cur[n + 2] + 3) >> 2;
        float2 accA, accB, accC;
        gather3(eg, wv, n * PAD, qcA, (n + 1) * PAD, qcB, (n + 2) * PAD, qcC,
                lane, accA, accB, accC);
        // prefetch epilogue operands under the mix
        int rA = n * 32 + lane, rB = rA + 32, rC = rB + 32;
        float2 bbA = ((const float2*)g_b)[rA], uuA = ((const float2*)usrc)[rA];
        float2 bbB = ((const float2*)g_b)[rB], uuB = ((const float2*)usrc)[rB];
        float2 bbC = ((const float2*)g_b)[rC], uuC = ((const float2*)usrc)[rC];
        __syncwarp();
        su->mix.s[warp][lane]  = make_ulonglong2(pack2(accA), pack2(accB));
        su->mix.s2[warp][lane] = pack2(accC);
        __syncwarp();
        ull PA = 0ull, QA = 0ull, PB = 0ull, QB = 0ull, PC = 0ull, QC = 0ull;
#pragma unroll
        for (int m = 0; m < 32; ++m) {
            ulonglong2 sp = su->mix.s[warp][m];
            ull spC       = su->mix.s2[warp][m];
            ulonglong2 T  = su->mix.T[m][lane];
            fma2(PA, T.x, sp.x); fma2(QA, T.y, sp.x);
            fma2(PB, T.x, sp.y); fma2(QB, T.y, sp.y);
            fma2(PC, T.x, spC);  fma2(QC, T.y, spC);
        }
        float2 pA = unpack2(PA), qA = unpack2(QA);
        float2 pB = unpack2(PB), qB = unpack2(QB);
        float2 pC = unpack2(PC), qC = unpack2(QC);
        epilogue(n,     lane, make_float2(pA.x + pA.y, qA.x + qA.y),
                 slot, npairs, wr_next, wr_g, bbA, uuA, wdst, p);
        epilogue(n + 1, lane, make_float2(pB.x + pB.y, qB.x + qB.y),
                 slot, npairs, wr_next, wr_g, bbB, uuB, wdst, p);
        epilogue(n + 2, lane, make_float2(pC.x + pC.y, qC.x + qC.y),
                 slot, npairs, wr_next, wr_g, bbC, uuC, wdst, p);
        n += 3;
    }

    // pairs
    for (; n + 1 < ne; n += 2) {
        int qcA = (g_cur[n] + 3) >> 2;
        int qcB = (g_cur[n + 1] + 3) >> 2;
        float2 accA, accB;
        gather2(eg, wv, n * PAD, qcA, (n + 1) * PAD, qcB, lane, accA, accB);
        int rA = n * 32 + lane, rB = rA + 32;
        float2 bbA = ((const float2*)g_b)[rA], uuA = ((const float2*)usrc)[rA];
        float2 bbB = ((const float2*)g_b)[rB], uuB = ((const float2*)usrc)[rB];
        __syncwarp();
        su->mix.s[warp][lane] = make_ulonglong2(pack2(accA), pack2(accB));
        __syncwarp();
        ull PA = 0ull, QA = 0ull, PB = 0ull, QB = 0ull;
#pragma unroll
        for (int m = 0; m < 32; ++m) {
            ulonglong2 sp = su->mix.s[warp][m];   // broadcast LDS.128
            ulonglong2 T  = su->mix.T[m][lane];   // conflict-free LDS.128
            fma2(PA, T.x, sp.x); fma2(QA, T.y, sp.x);
            fma2(PB, T.x, sp.y); fma2(QB, T.y, sp.y);
        }
        float2 pA = unpack2(PA), qA = unpack2(QA);
        float2 pB = unpack2(PB), qB = unpack2(QB);
        epilogue(n,     lane, make_float2(pA.x + pA.y, qA.x + qA.y),
                 slot, npairs, wr_next, wr_g, bbA, uuA, wdst, p);
        epilogue(n + 1, lane, make_float2(pB.x + pB.y, qB.x + qB.y),
                 slot, npairs, wr_next, wr_g, bbB, uuB, wdst, p);
    }
    // single
    if (n < ne) {
        int qcA = (g_cur[n] + 3) >> 2;
        float2 acc, dummy;
        gather2(eg, wv, n * PAD, qcA, n * PAD, 0, lane, acc, dummy);
        int rA = n * 32 + lane;
        float2 bbA = ((const float2*)g_b)[rA], uuA = ((const float2*)usrc)[rA];
        __syncwarp();
        su->mix.s[warp][lane] = make_ulonglong2(pack2(acc), 0ull);
        __syncwarp();
        ull PA = 0ull, QA = 0ull;
#pragma unroll
        for (int m = 0; m < 32; ++m) {
            ulonglong2 sp = su->mix.s[warp][m];
            ulonglong2 T  = su->mix.T[m][lane];
            fma2(PA, T.x, sp.x);
            fma2(QA, T.y, sp.x);
        }
        float2 pA = unpack2(PA), qA = unpack2(QA);
        epilogue(n, lane, make_float2(pA.x + pA.y, qA.x + qA.y),
                 slot, npairs, wr_next, wr_g, bbA, uuA, wdst, p);
    }

#pragma unroll
    for (int j = 0; j < 5; ++j)
        for (int off = 16; off > 0; off >>= 1)
            p[j] += __shfl_down_sync(0xffffffffu, p[j], off);
    __syncthreads();
    if (lane == 0)
        for (int j = 0; j < 5; ++j) red[warp][j] = (double)p[j];
    __syncthreads();
    if (threadIdx.x < npairs) {
        int j = threadIdx.x;
        double s = 0.0;
        for (int ww = 0; ww < WPB; ww++) s += red[ww][j];
        atomicAdd(&target[j], s);
    }
}

// ---------------- combine(k): Gram merge + 5x5 solve + u_new (+ fused decode at k=4) ----------------
__device__ void combine_phase(int k, float* sa, const float* __restrict__ decW,
                              float* __restrict__ out) {
    int warp = threadIdx.x >> 5, lane = threadIdx.x & 31;
    int g = blockIdx.x * WPB + warp;
    const float2* F0 = (const float2*)g_F[0];
    const float2* F1 = (const float2*)g_F[1];
    const float2* F2 = (const float2*)g_F[2];
    const float2* F3 = (const float2*)g_F[3];
    const float2* F4 = (const float2*)g_F[4];

    // preload first node's F rows; latency hides under the solve below
    int idx0 = g * 32 + lane;
    float2 pf0 = F0[idx0], pf1 = F1[idx0], pf2 = F2[idx0], pf3 = F3[idx0], pf4 = F4[idx0];

    if (threadIdx.x == 0) {
        double M[5][5];
        const double* base = g_GGbuf[k & 1];
        int c = 0;
        for (int i = 0; i < 5; i++)
            for (int j = 0; j <= i; j++) { M[i][j] = base[c]; M[j][i] = base[c]; c++; }
        if (k > 0) {
            int idx = k - 1;
            const double* row = g_GGrow[(k - 1) & 1];
            for (int j = 0; j < 5; j++) { M[idx][j] = row[j]; M[j][idx] = row[j]; }
        }
        if (blockIdx.x == 0 && k < AAM - 1) {
            c = 0;
            for (int i = 0; i < 5; i++)
                for (int j = 0; j <= i; j++) g_GGbuf[(k + 1) & 1][c++] = M[i][j];
            for (int j = 0; j < 5; j++) g_GGrow[k & 1][j] = 0.0;
        }
        float A[5][6];
        for (int i = 0; i < 5; i++) {
            for (int j = 0; j < 5; j++) A[i][j] = (float)M[i][j];
            A[i][i] += 1e-4f;
            A[i][5] = 1.f;
        }
        for (int kk = 0; kk < 5; kk++) {
            int piv = kk; float mx = fabsf(A[kk][kk]);
            for (int r = kk + 1; r < 5; r++)
                if (fabsf(A[r][kk]) > mx) { mx = fabsf(A[r][kk]); piv = r; }
            if (piv != kk)
                for (int j = 0; j < 6; j++) { float t = A[kk][j]; A[kk][j] = A[piv][j]; A[piv][j] = t; }
            float inv = 1.f / A[kk][kk];
            for (int r = kk + 1; r < 5; r++) {
                float f = A[r][kk] * inv;
                for (int j = kk; j < 6; j++) A[r][j] -= f * A[kk][j];
            }
        }
        float a[5];
        for (int kk = 4; kk >= 0; kk--) {
            float s = A[kk][5];
            for (int j = kk + 1; j < 5; j++) s -= A[kk][j] * a[j];
            a[kk] = s / A[kk][kk];
        }
        float sum = a[0] + a[1] + a[2] + a[3] + a[4];
        for (int j = 0; j < 5; j++) sa[j] = a[j] / sum;
    }
    __syncthreads();
    float a0 = sa[0], a1 = sa[1], a2 = sa[2], a3 = sa[3], a4 = sa[4];

    for (int node = g; node < N_NODES; node += NWARPS) {
        int idx = node * 32 + lane;
        float2 f0, f1, f2, f3, f4;
        if (node == g) { f0 = pf0; f1 = pf1; f2 = pf2; f3 = pf3; f4 = pf4; }
        else { f0 = F0[idx]; f1 = F1[idx]; f2 = F2[idx]; f3 = F3[idx]; f4 = F4[idx]; }
        float2 un;
        un.x = a0 * f0.x + a1 * f1.x + a2 * f2.x + a3 * f3.x + a4 * f4.x;
        un.y = a0 * f0.y + a1 * f1.y + a2 * f2.y + a3 * f3.y + a4 * f4.y;
        if (k < AAM - 1) {
            ((float2*)g_u)[idx] = un;
            float2 bb = ((const float2*)g_b)[idx];
            ((__half2*)g_wbuf[0])[idx] =
                __floats2half2_rn(2.f * fmaxf(un.x, 0.f) - un.x + bb.x,
                                  2.f * fmaxf(un.y, 0.f) - un.y + bb.y);
        } else {
            float rx = fmaxf(un.x, 0.f), ry = fmaxf(un.y, 0.f);
            int o = lane & 15, half = lane >> 4;
            float acc = 0.f;
#pragma unroll
            for (int i = 0; i < 16; i++) {
                int m = half * 16 + i;
                float sx = __shfl_sync(0xffffffffu, rx, m);
                float sy = __shfl_sync(0xffffffffu, ry, m);
                acc = fmaf(sx, decW[(2 * m) * 16 + o], acc);
                acc = fmaf(sy, decW[(2 * m + 1) * 16 + o], acc);
            }
            acc += __shfl_down_sync(0xffffffffu, acc, 16);
            if (half == 0) out[node * 16 + o] = acc;
        }
    }
}

// ---------------- the single persistent kernel ----------------
__global__ void __launch_bounds__(TPB, BLK_PER_SM) k_mega(
    const float* __restrict__ x, const int* __restrict__ ei,
    const float* __restrict__ ew, const float* __restrict__ encW,
    const float* __restrict__ encb, const float* __restrict__ cayB,
    const float* __restrict__ decW, float* __restrict__ out)
{
    __shared__ SmemU su;
    __shared__ double red[WPB][5];
    __shared__ float sa[5];

    const int* src = ei;
    const int* dst = ei + N_EDGES;
    int gtid = blockIdx.x * TPB + threadIdx.x;

    // Phase 1: one-pass padded-row scatter (g_cur pre-zeroed) || encoder || zero GGbuf[0]
    for (int e = gtid; e < N_EDGES; e += NTHREADS) {
        int d = dst[e];
        int pos = atomicAdd(&g_cur[d], 1);
        uint packed = (uint)src[e]
                    | ((uint)__half_as_ushort(__float2half_rn(ew[e])) << 16);
        g_edge[d * PAD + pos] = packed;
    }
    if (gtid < 15) g_GGbuf[0][gtid] = 0.0;
    encode_phase(x, encW, encb, &su);
    gbar();

    // Phase 2: count-prefix scan (block 0) || Cayley theta (block 1)
    //          || zero-fill row padding to multiple of 4 edges (blocks >= 2)
    if (blockIdx.x == 0) {
        int t = threadIdx.x;
        const int CH = (N_NODES + TPB - 1) / TPB;   // 20
        int beg = t * CH, end = beg + CH; if (end > N_NODES) end = N_NODES;
        int s = 0;
        for (int i = beg; i < end; i++) s += g_cur[i];
        su.part[t] = s;
        __syncthreads();
        for (int d = 1; d < TPB; d <<= 1) {
            int v = (t >= d) ? su.part[t - d] : 0;
            __syncthreads();
            su.part[t] += v;
            __syncthreads();
        }
        int off = (t > 0) ? su.part[t - 1] : 0;
        for (int i = beg; i < end; i++) {
            g_rowptr[i] = off;
            off += g_cur[i];
        }
        if (t == 0) g_rowptr[N_NODES] = N_EDGES;
    } else if (blockIdx.x == 1) {
        theta_phase(cayB, &su);
    } else {
        int base = (blockIdx.x - 2) * TPB + threadIdx.x;
        for (int i = base; i < N_NODES; i += (GRID_BLOCKS - 2) * TPB) {
            int c = g_cur[i];
            int cr = (c + 3) & ~3;
            for (int e = c; e < cr; e++)
                g_edge[i * PAD + e] = 0u;   // src 0, w = 0.0h
        }
    }
    gbar();

    // Phase 3: balanced warp partition || stage packed Theta
    if (gtid <= NWARPS) {
        if (gtid == NWARPS) {
            g_wstart[NWARPS] = N_NODES;
        } else {
            long long target = (long long)gtid * COST_TOTAL / NWARPS;
            int lo = 0, hi = N_NODES;
            while (lo < hi) {
                int mid = (lo + hi) >> 1;
                long long c = (long long)g_rowptr[mid] + (long long)NODE_COST * mid;
                if (c < target) lo = mid + 1; else hi = mid;
            }
            g_wstart[gtid] = lo;
        }
    }
    for (int i = threadIdx.x; i < 1024; i += TPB) {
        int m = i >> 5, l = i & 31;
        float a0 = g_ThT[(2 * m) * 64 + 2 * l];
        float a1 = g_ThT[(2 * m + 1) * 64 + 2 * l];
        float b0 = g_ThT[(2 * m) * 64 + 2 * l + 1];
        float b1 = g_ThT[(2 * m + 1) * 64 + 2 * l + 1];
        su.mix.T[m][l] = make_ulonglong2(pack2(make_float2(a0, a1)),
                                         pack2(make_float2(b0, b1)));
    }
    gbar();

    // history: 5 PR sweeps (w ping-pong); uu read from b / F[i-1]
    for (int i = 0; i < AAM; i++) {
        spmm_phase(i, i + 1, &g_GGbuf[0][i * (i + 1) / 2], (i < AAM - 1) ? 1 : 0, 1,
                   g_wbuf[i & 1], (i == 0) ? g_b : g_F[i - 1], g_wbuf[(i + 1) & 1],
                   &su, red);
        gbar();
    }

    // Anderson: combine -> spmm (last g() dead); final combine fuses decode.
    for (int k = 0; k < AAM; k++) {
        combine_phase(k, sa, decW, out);
        if (k < AAM - 1) {
            gbar();
            spmm_phase(k, 5, g_GGrow[k & 1], 0, (k < AAM - 2) ? 1 : 0,
                       g_wbuf[0], g_u, 0, &su, red);
            gbar();
        }
    }

    // tail: re-zero g_cur for the NEXT launch
    for (int i = gtid; i < N_NODES; i += NTHREADS) g_cur[i] = 0;
}

// ---------------- launch: ONE kernel ----------------
extern "C" void kernel_launch(void* const* d_in, const int* in_sizes, int n_in,
                              void* d_out, int out_size) {
    const float* x    = (const float*)d_in[0];
    const int*   ei   = (const int*)  d_in[1];
    const float* ew   = (const float*)d_in[2];
    const float* encW = (const float*)d_in[3];
    const float* encb = (const float*)d_in[4];
    const float* cayB = (const float*)d_in[5];
    const float* decW = (const float*)d_in[6];
    float* out = (float*)d_out;

    k_mega<<<GRID_BLOCKS, TPB>>>(x, ei, ew, encW, encb, cayB, decW, out);
}